// round 10
// baseline (speedup 1.0000x reference)
#include <cuda_runtime.h>
#include <math.h>
#include <stdint.h>

#define NB 4
#define NT 512
#define DMODEL 769
#define DINNER 1538
#define DSTATE 64
#define DTRANK 49
#define BT (NB*NT)            // 2048 rows
#define XPROJ_N 177           // DT_RANK + 2*D_STATE
#define LDA_IN 800            // padded ld for in_proj operands (25 k-tiles)
#define LDA_OUT 1568          // padded ld for out_proj operands (49 k-tiles)

// ---------------- scratch (static device globals; zero-initialized) -------------
__device__ float g_xT [NB*64*NT];           // x transposed (B,64,T)
__device__ float g_h0 [NB*128*NT];          // pointconv out (B,128,T)
__device__ float g_h2 [NB*768*NT];          // conv stack out (B,768,T)
__device__ float g_h  [BT*DMODEL];          // residual stream (B,T,769)
__device__ __align__(16) float g_unp[BT*LDA_IN];        // normalized, padded ld 800
__device__ __align__(16) float g_wi [2*2*DINNER*LDA_IN];// in_proj W padded
__device__ __align__(16) float g_wo [2*DMODEL*LDA_OUT]; // out_proj W padded
__device__ __align__(16) float g_yp [BT*LDA_OUT];       // scan out, padded ld 1568
__device__ float g_xz [BT*2*DINNER];        // in_proj out (B,T,3076)
__device__ float g_xin[BT*DINNER];          // post dw-conv silu
__device__ float g_dbc[BT*XPROJ_N];         // x_proj out
__device__ float g_dt [BT*DINNER];          // softplus(dt)

__device__ __forceinline__ float silu_f(float v){ return v / (1.f + __expf(-v)); }

// ---- tf32 mma (raw-bit truncation; fp32 bits are valid tf32 input) ----
__device__ __forceinline__ void mma_tf32(float* c, const uint32_t* a, const uint32_t* b){
    asm("mma.sync.aligned.m16n8k8.row.col.f32.tf32.tf32.f32 "
        "{%0,%1,%2,%3}, {%4,%5,%6,%7}, {%8,%9}, {%0,%1,%2,%3};"
        : "+f"(c[0]), "+f"(c[1]), "+f"(c[2]), "+f"(c[3])
        : "r"(a[0]), "r"(a[1]), "r"(a[2]), "r"(a[3]), "r"(b[0]), "r"(b[1]));
}

// ---------------- weight repack into padded layout (pads stay zero) -------------
__global__ void k_packw(const float* __restrict__ src, float* __restrict__ dst,
                        int rows, int K, int ldd){
    int idx = blockIdx.x*256 + threadIdx.x;
    if (idx >= rows*K) return;
    int r = idx / K, c = idx - r*K;
    dst[(size_t)r*ldd + c] = src[idx];
}

// ---------------- x (B,T,65) -> g_xT (B,64,T) ----------------
__global__ void k_xt(const float* __restrict__ x){
    __shared__ float tile[32][33];
    int b  = blockIdx.z;
    int t0 = blockIdx.x*32, c0 = blockIdx.y*32;
    int tx = threadIdx.x, ty = threadIdx.y;
    tile[ty][tx] = x[(b*NT + t0 + ty)*65 + c0 + tx];
    __syncthreads();
    g_xT[(b*64 + c0 + ty)*NT + t0 + tx] = tile[tx][ty];
}

// ---------------- front: pointwise conv (64->128) + silu (coalesced) ------------
__global__ void k_pointconv(const float* __restrict__ pw,
                            const float* __restrict__ pb){
    int idx = blockIdx.x*256 + threadIdx.x;
    int t = idx & 511;
    int c = (idx >> 9) & 127;
    int b = idx >> 16;
    const float* xr = g_xT + b*64*NT + t;
    const float* wr = pw + c*64;
    float acc = pb[c];
#pragma unroll
    for (int i = 0; i < 64; i++) acc += xr[i*NT]*wr[i];
    g_h0[(b*128 + c)*NT + t] = silu_f(acc);
}

// ---- front conv v5: 8 ocs per block, T split in 4 quarters (grid 512) ----
template<int KS>
__global__ void k_conv(const float* __restrict__ w,
                       const float* __restrict__ bias,
                       int ocBase){
    __shared__ float ws[8][8*KS];
    __shared__ float xs[8][160];
    const int tid = threadIdx.x;
    const int b   = blockIdx.x >> 7;
    const int rem = blockIdx.x & 127;
    const int ocg = rem >> 2;
    const int tq  = rem & 3;
    const int oc0 = ocg*8;
    const int tbase = tq*128;
    const int pad = (KS - 1)/2;
    const int oc_sub = tid >> 7;
    const int tc  = tid & 127;

    float acc[4];
#pragma unroll
    for (int ol = 0; ol < 4; ol++) acc[ol] = bias[oc0 + oc_sub*4 + ol];

    for (int icb = 0; icb < 128; icb += 8){
        __syncthreads();
        for (int i = tid; i < 8*155; i += 256){
            int r = i / 155, j = i - r*155;
            int tt = tbase + j - 13;
            const float* hrow = g_h0 + (b*128 + icb + r)*NT;
            xs[r][j] = (tt >= 0 && tt < NT) ? hrow[tt] : 0.f;
        }
        for (int i = tid; i < 8*8*KS; i += 256){
            int oc = i / (8*KS), j = i - oc*(8*KS);
            ws[oc][j] = w[(oc0 + oc)*128*KS + icb*KS + j];
        }
        __syncthreads();
#pragma unroll
        for (int r = 0; r < 8; r++){
            float xv[KS];
            const int base = tc + 13 - pad;
#pragma unroll
            for (int q = 0; q < KS; q++) xv[q] = xs[r][base + q];
#pragma unroll
            for (int ol = 0; ol < 4; ol++){
                const float* wr = &ws[oc_sub*4 + ol][r*KS];
#pragma unroll
                for (int k = 0; k < KS; k++) acc[ol] += wr[k]*xv[k];
            }
        }
    }
#pragma unroll
    for (int ol = 0; ol < 4; ol++)
        g_h2[(b*768 + ocBase + oc0 + oc_sub*4 + ol)*NT + tbase + tc] = silu_f(acc[ol]);
}

// ---------------- (B,C,T) -> (B,T,769) transpose ----------------
__global__ void k_transpose(){
    __shared__ float tile[32][33];
    int b  = blockIdx.z;
    int t0 = blockIdx.x*32, c0 = blockIdx.y*32;
    int tx = threadIdx.x, ty = threadIdx.y;
    tile[ty][tx] = g_h2[(b*768 + c0 + ty)*NT + t0 + tx];
    __syncthreads();
    g_h[(b*NT + t0 + ty)*DMODEL + c0 + tx] = tile[tx][ty];
}

__global__ void k_pe(const float* __restrict__ x){
    int i = blockIdx.x*256 + threadIdx.x;
    if (i >= BT) return;
    g_h[i*DMODEL + 768] = x[i*65 + 64];
}

// ---------------- rmsnorm (writes padded g_unp) / layernorm ----------------
__global__ void k_rmsnorm(const float* __restrict__ w){
    int m = blockIdx.x, tid = threadIdx.x;
    const float* row = g_h + m*DMODEL;
    float s = 0.f;
    for (int k = tid; k < DMODEL; k += 256){ float v = row[k]; s += v*v; }
#pragma unroll
    for (int o = 16; o > 0; o >>= 1) s += __shfl_xor_sync(0xffffffffu, s, o);
    __shared__ float red[8];
    if ((tid & 31) == 0) red[tid >> 5] = s;
    __syncthreads();
    s = red[0]+red[1]+red[2]+red[3]+red[4]+red[5]+red[6]+red[7];
    float sc = rsqrtf(s/769.f + 1e-6f);
    float* o = g_unp + (size_t)m*LDA_IN;
    for (int k = tid; k < DMODEL; k += 256) o[k] = row[k]*sc*w[k];
}

__global__ void k_layernorm(const float* __restrict__ w, const float* __restrict__ bb){
    int m = blockIdx.x, tid = threadIdx.x;
    const float* row = g_h + m*DMODEL;
    float s1 = 0.f, s2 = 0.f;
    for (int k = tid; k < DMODEL; k += 256){ float v = row[k]; s1 += v; s2 += v*v; }
#pragma unroll
    for (int o = 16; o > 0; o >>= 1){
        s1 += __shfl_xor_sync(0xffffffffu, s1, o);
        s2 += __shfl_xor_sync(0xffffffffu, s2, o);
    }
    __shared__ float r1[8], r2[8];
    if ((tid & 31) == 0){ r1[tid >> 5] = s1; r2[tid >> 5] = s2; }
    __syncthreads();
    s1 = 0.f; s2 = 0.f;
#pragma unroll
    for (int i = 0; i < 8; i++){ s1 += r1[i]; s2 += r2[i]; }
    float mean = s1/769.f;
    float var  = s2/769.f - mean*mean;
    float istd = rsqrtf(var + 1e-5f);
    float* o = g_unp + (size_t)m*LDA_IN;
    for (int k = tid; k < DMODEL; k += 256)
        o[k] = (row[k] - mean)*istd*w[k] + bb[k];
}

// ---------------- tf32 MMA GEMM 128xBNx32, double-buffered ----------------------
// NJ = BN/16 (8 -> BN=128, 4 -> BN=64). Padded operands (lda/ldw multiple of 32,
// zero pads). epi: 0 = store, 2 = C += acc. Dynamic smem:
//   Ap[2][4096] then Bp[2][NJ*512]  (uint32)
template<int NJ>
__global__ void __launch_bounds__(256, 1)
k_mma128(const float* __restrict__ A, int lda,
         const float* __restrict__ W, int ldw,
         float* __restrict__ C, int ldc,
         int M, int N, int K, int epi){
    extern __shared__ uint32_t smem[];
    const int BN   = NJ*16;
    const int BPSZ = NJ*512;            // per-buffer B words
    uint32_t* Ap = smem;                // [2][4096]
    uint32_t* Bp = smem + 2*4096;       // [2][BPSZ]

    const int tid  = threadIdx.x;
    const int lane = tid & 31;
    const int wid  = tid >> 5;
    const int warp_m = wid & 3, warp_n = wid >> 2;
    const int m0 = blockIdx.y*128, n0 = blockIdx.x*BN;

    const int sr  = tid >> 1;           // 0..127
    const int skb = (tid & 1) * 16;

    const bool okA = (m0 + sr) < M;
    const bool okW = (sr < BN) && ((n0 + sr) < N);
    const float* Arow = A + (size_t)(m0 + sr)*lda + skb;
    const float* Wrow = W + (size_t)(n0 + sr)*ldw + skb;

    // scatter constants (PTX m16n8k8 fragment layouts)
    const int a_blk0 = ((sr>>5)*2 + ((sr>>4)&1))*4;
    const int a_lb   = (sr&7)*4;
    const int a_him  = (sr>>3)&1;
    const int b_blk0 = (sr>>3)*4;       // == (warp_n_of_row*NJ + j_of_row)*4
    const int b_lb   = (sr&7)*4;

    float acc[2][NJ][4];
#pragma unroll
    for (int i = 0; i < 2; i++)
#pragma unroll
        for (int j = 0; j < NJ; j++)
#pragma unroll
            for (int q = 0; q < 4; q++) acc[i][j][q] = 0.f;

    const int nk = (K + 31) >> 5;
    float4 ra4[4], rb4[4];
    float* ra = (float*)ra4;
    float* rb = (float*)rb4;

    // prefetch tile 0
#pragma unroll
    for (int q = 0; q < 4; q++){
        ra4[q] = okA ? ((const float4*)Arow)[q] : make_float4(0.f,0.f,0.f,0.f);
        rb4[q] = okW ? ((const float4*)Wrow)[q] : make_float4(0.f,0.f,0.f,0.f);
    }
    // store tile 0 into buffer 0
    {
#pragma unroll
        for (int q = 0; q < 16; q++){
            int kch = (skb + q) >> 3, klow = (skb + q) & 7;
            Ap[(a_blk0 + kch)*128 + (a_lb + (klow&3))*4 + a_him + 2*(klow>>2)] = __float_as_uint(ra[q]);
        }
        if (okW){
#pragma unroll
            for (int kch2 = 0; kch2 < 2; kch2++){
                int kch = (skb >> 3) + kch2;
#pragma unroll
                for (int q = 0; q < 4; q++){
                    uint2 v = make_uint2(__float_as_uint(rb[kch2*8 + q]),
                                         __float_as_uint(rb[kch2*8 + q + 4]));
                    *(uint2*)&Bp[(b_blk0 + kch)*64 + (b_lb + q)*2] = v;
                }
            }
        }
    }
    __syncthreads();

    int buf = 0;
    for (int kt = 0; kt < nk; kt++){
        if (kt + 1 < nk){
            int k0 = (kt + 1)*32;
#pragma unroll
            for (int q = 0; q < 4; q++){
                ra4[q] = okA ? ((const float4*)(Arow + k0))[q] : make_float4(0.f,0.f,0.f,0.f);
                rb4[q] = okW ? ((const float4*)(Wrow + k0))[q] : make_float4(0.f,0.f,0.f,0.f);
            }
        }

        const uint32_t* Apb = Ap + buf*4096;
        const uint32_t* Bpb = Bp + buf*BPSZ;
#pragma unroll
        for (int kch = 0; kch < 4; kch++){
            uint32_t af[2][4], bf[NJ][2];
#pragma unroll
            for (int i = 0; i < 2; i++){
                uint4 v = *(const uint4*)&Apb[((warp_m*2 + i)*4 + kch)*128 + lane*4];
                af[i][0] = v.x; af[i][1] = v.y; af[i][2] = v.z; af[i][3] = v.w;
            }
#pragma unroll
            for (int j = 0; j < NJ; j++){
                uint2 v = *(const uint2*)&Bpb[((warp_n*NJ + j)*4 + kch)*64 + lane*2];
                bf[j][0] = v.x; bf[j][1] = v.y;
            }
#pragma unroll
            for (int i = 0; i < 2; i++)
#pragma unroll
                for (int j = 0; j < NJ; j++) mma_tf32(acc[i][j], af[i], bf[j]);
        }

        if (kt + 1 < nk){
            int nb = buf ^ 1;
            uint32_t* Apn = Ap + nb*4096;
            uint32_t* Bpn = Bp + nb*BPSZ;
#pragma unroll
            for (int q = 0; q < 16; q++){
                int kch = (skb + q) >> 3, klow = (skb + q) & 7;
                Apn[(a_blk0 + kch)*128 + (a_lb + (klow&3))*4 + a_him + 2*(klow>>2)] = __float_as_uint(ra[q]);
            }
            if (okW){
#pragma unroll
                for (int kch2 = 0; kch2 < 2; kch2++){
                    int kch = (skb >> 3) + kch2;
#pragma unroll
                    for (int q = 0; q < 4; q++){
                        uint2 v = make_uint2(__float_as_uint(rb[kch2*8 + q]),
                                             __float_as_uint(rb[kch2*8 + q + 4]));
                        *(uint2*)&Bpn[(b_blk0 + kch)*64 + (b_lb + q)*2] = v;
                    }
                }
            }
            __syncthreads();
            buf = nb;
        }
    }

    const int r_c = lane >> 2, c_c = (lane & 3)*2;
#pragma unroll
    for (int i = 0; i < 2; i++){
        int gmA0 = m0 + warp_m*32 + i*16 + r_c;
#pragma unroll
        for (int j = 0; j < NJ; j++){
            int gn = n0 + warp_n*(NJ*8) + j*8 + c_c;
#pragma unroll
            for (int h = 0; h < 2; h++){
                int gm = gmA0 + h*8;
                if (gm >= M) continue;
                float* crow = C + (size_t)gm*ldc;
                float v0 = acc[i][j][2*h], v1 = acc[i][j][2*h + 1];
                if (epi == 2){
                    if (gn     < N) crow[gn]     += v0;
                    if (gn + 1 < N) crow[gn + 1] += v1;
                } else {
                    if (gn     < N) crow[gn]     = v0;
                    if (gn + 1 < N) crow[gn + 1] = v1;
                }
            }
        }
    }
}

// ---------------- SGEMM 64x64 fp32: C = epi(A(MxK) * W(NxK)^T) ------------------
// epi: 0 = none, 1 = bias + softplus
__global__ void k_sgemm64(const float* __restrict__ A, int lda,
                          const float* __restrict__ W, int ldw,
                          float* __restrict__ C, int ldc,
                          int M, int N, int K,
                          const float* __restrict__ bias, int epi){
    __shared__ __align__(16) float As[16][68];
    __shared__ __align__(16) float Ws[16][68];
    const int tid = threadIdx.x;
    const int m0 = blockIdx.y*64, n0 = blockIdx.x*64;
    const int tx = tid & 15, ty = tid >> 4;

    float acc[4][4];
#pragma unroll
    for (int i = 0; i < 4; i++)
#pragma unroll
        for (int j = 0; j < 4; j++) acc[i][j] = 0.f;

    for (int k0 = 0; k0 < K; k0 += 16){
        for (int i = tid; i < 1024; i += 256){
            int mm = i >> 4, kk = i & 15;
            int gk = k0 + kk;
            int gm = m0 + mm;
            As[kk][mm] = (gm < M && gk < K) ? A[gm*lda + gk] : 0.f;
            int gn = n0 + mm;
            Ws[kk][mm] = (gn < N && gk < K) ? W[gn*ldw + gk] : 0.f;
        }
        __syncthreads();
#pragma unroll
        for (int kk = 0; kk < 16; kk++){
            float4 a4 = *(const float4*)&As[kk][ty*4];
            float4 w4 = *(const float4*)&Ws[kk][tx*4];
            float av[4] = {a4.x, a4.y, a4.z, a4.w};
            float wv[4] = {w4.x, w4.y, w4.z, w4.w};
#pragma unroll
            for (int i = 0; i < 4; i++)
#pragma unroll
                for (int j = 0; j < 4; j++) acc[i][j] += av[i]*wv[j];
        }
        __syncthreads();
    }

#pragma unroll
    for (int i = 0; i < 4; i++){
        int gm = m0 + ty*4 + i;
        if (gm >= M) continue;
#pragma unroll
        for (int j = 0; j < 4; j++){
            int gn = n0 + tx*4 + j;
            if (gn >= N) continue;
            float v = acc[i][j];
            float* cp = &C[gm*ldc + gn];
            if (epi == 1){
                v += bias[gn];
                v = fmaxf(v, 0.f) + log1pf(expf(-fabsf(v)));   // stable softplus
                *cp = v;
            } else {
                *cp = v;
            }
        }
    }
}

// ---------------- depthwise causal conv (k=4) + silu ----------------
__global__ void k_dwconv(const float* __restrict__ cw, const float* __restrict__ cb){
    int idx = blockIdx.x*256 + threadIdx.x;
    int d  = idx % DINNER;
    int bt = idx / DINNER;
    int t  = bt & 511;
    float acc = cb[d];
#pragma unroll
    for (int k = 0; k < 4; k++){
        int tt = t - 3 + k;
        if (tt >= 0) acc += cw[d*4 + k] * g_xz[(bt - 3 + k)*2*DINNER + d];
    }
    g_xin[bt*DINNER + d] = silu_f(acc);
}

// ---------------- selective scan: warp per (b,d), 2 states/lane ----------------
__global__ void k_scan(const float* __restrict__ Alog, const float* __restrict__ Dv){
    int w    = blockIdx.x*4 + (threadIdx.x >> 5);
    int lane = threadIdx.x & 31;
    int b = w & 3;
    int d = w >> 2;

    float A1 = -__expf(Alog[d*64 + lane]);
    float A2 = -__expf(Alog[d*64 + lane + 32]);
    float Dd = Dv[d];
    float h1 = 0.f, h2 = 0.f;

    int r = b*NT;
    for (int t = 0; t < NT; t++, r++){
        float dtv = g_dt [r*DINNER + d];
        float uv  = g_xin[r*DINNER + d];
        const float* q = g_dbc + r*XPROJ_N;
        float B1 = q[49  + lane], B2 = q[81  + lane];
        float C1 = q[113 + lane], C2 = q[145 + lane];
        float du = dtv*uv;
        h1 = __expf(dtv*A1)*h1 + du*B1;
        h2 = __expf(dtv*A2)*h2 + du*B2;
        float p = h1*C1 + h2*C2;
#pragma unroll
        for (int o = 16; o > 0; o >>= 1) p += __shfl_xor_sync(0xffffffffu, p, o);
        if (lane == 0){
            float zv = g_xz[r*2*DINNER + DINNER + d];
            g_yp[(size_t)r*LDA_OUT + d] = (p + uv*Dd) * silu_f(zv);
        }
    }
}

// ---------------- classifier: warp per (row, class) ----------------
__global__ void k_classifier(const float* __restrict__ ow,
                             const float* __restrict__ ob,
                             float* __restrict__ out){
    int m = blockIdx.x;
    int wid  = threadIdx.x >> 5;
    int lane = threadIdx.x & 31;
    const float* u  = g_unp + (size_t)m*LDA_IN;
    const float* wr = ow + wid*DMODEL;
    float s = 0.f;
    for (int k = lane; k < DMODEL; k += 32) s += u[k]*wr[k];
#pragma unroll
    for (int o = 16; o > 0; o >>= 1) s += __shfl_xor_sync(0xffffffffu, s, o);
    if (lane == 0) out[m*10 + wid] = s + ob[wid];
}

// ---------------- orchestration ----------------
extern "C" void kernel_launch(void* const* d_in, const int* in_sizes, int n_in,
                              void* d_out, int out_size){
    const float* x    = (const float*)d_in[0];
    const float* pw   = (const float*)d_in[1];
    const float* pb   = (const float*)d_in[2];
    const float* c1w  = (const float*)d_in[3];
    const float* c1b  = (const float*)d_in[4];
    const float* c2w  = (const float*)d_in[5];
    const float* c2b  = (const float*)d_in[6];
    const float* c3w  = (const float*)d_in[7];
    const float* c3b  = (const float*)d_in[8];
    const float* lnw  = (const float*)d_in[9];
    const float* lnb  = (const float*)d_in[10];
    const float* ow   = (const float*)d_in[11];
    const float* ob   = (const float*)d_in[12];
    const float* rmsw = (const float*)d_in[13];
    const float* inw  = (const float*)d_in[14];
    const float* dww  = (const float*)d_in[15];
    const float* dwb  = (const float*)d_in[16];
    const float* xpw  = (const float*)d_in[17];
    const float* dtw  = (const float*)d_in[18];
    const float* dtb  = (const float*)d_in[19];
    const float* alog = (const float*)d_in[20];
    const float* dsk  = (const float*)d_in[21];
    const float* opw  = (const float*)d_in[22];

    float *p_unp, *p_xz, *p_xin, *p_dbc, *p_dt, *p_yp, *p_h, *p_wi, *p_wo;
    cudaGetSymbolAddress((void**)&p_unp, g_unp);
    cudaGetSymbolAddress((void**)&p_xz,  g_xz);
    cudaGetSymbolAddress((void**)&p_xin, g_xin);
    cudaGetSymbolAddress((void**)&p_dbc, g_dbc);
    cudaGetSymbolAddress((void**)&p_dt,  g_dt);
    cudaGetSymbolAddress((void**)&p_yp,  g_yp);
    cudaGetSymbolAddress((void**)&p_h,   g_h);
    cudaGetSymbolAddress((void**)&p_wi,  g_wi);
    cudaGetSymbolAddress((void**)&p_wo,  g_wo);

    // dynamic smem opt-in for the double-buffered mma kernels
    cudaFuncSetAttribute(k_mma128<8>, cudaFuncAttributeMaxDynamicSharedMemorySize, 65536);
    cudaFuncSetAttribute(k_mma128<4>, cudaFuncAttributeMaxDynamicSharedMemorySize, 49152);

    // weight repacks into padded layout (pads stay zero from static init)
    k_packw<<<(2*2*DINNER*DMODEL + 255)/256, 256>>>(inw, p_wi, 2*2*DINNER, DMODEL, LDA_IN);
    k_packw<<<(2*DMODEL*DINNER + 255)/256, 256>>>(opw, p_wo, 2*DMODEL, DINNER, LDA_OUT);

    k_xt<<<dim3(16, 2, 4), dim3(32, 32)>>>(x);
    k_pointconv<<<1024, 256>>>(pw, pb);
    k_conv<3> <<<512, 256>>>(c1w, c1b, 0);
    k_conv<9> <<<512, 256>>>(c2w, c2b, 256);
    k_conv<27><<<512, 256>>>(c3w, c3b, 512);
    k_transpose<<<dim3(16, 24, 4), dim3(32, 32)>>>();
    k_pe<<<8, 256>>>(x);

    for (int l = 0; l < 2; l++){
        k_rmsnorm<<<2048, 256>>>(rmsw + l*DMODEL);
        // xz = un @ Wi^T       (2048 x 3076, K=769)  tf32 mma BN=128, 400 blocks
        k_mma128<8><<<dim3(25, 16), 256, 65536>>>(p_unp, LDA_IN,
                                        p_wi + (size_t)l*2*DINNER*LDA_IN, LDA_IN,
                                        p_xz, 2*DINNER,
                                        BT, 2*DINNER, DMODEL, 0);
        k_dwconv<<<12304, 256>>>(dww + l*DINNER*4, dwb + l*DINNER);
        // dbc = xin @ Wx^T     (2048 x 177, K=1538)  fp32 64x64
        k_sgemm64<<<dim3(3, 32), 256>>>(p_xin, DINNER,
                                        xpw + (size_t)l*XPROJ_N*DINNER, DINNER,
                                        p_dbc, XPROJ_N,
                                        BT, XPROJ_N, DINNER, nullptr, 0);
        // dt = softplus(dbc[:, :49] @ Wdt^T + bdt)   (2048 x 1538, K=49)
        k_sgemm64<<<dim3(25, 32), 256>>>(p_dbc, XPROJ_N,
                                         dtw + (size_t)l*DINNER*DTRANK, DTRANK,
                                         p_dt, DINNER,
                                         BT, DINNER, DTRANK, dtb + l*DINNER, 1);
        k_scan<<<1538, 128>>>(alog + (size_t)l*DINNER*DSTATE, dsk + l*DINNER);
        // h += y @ Wo^T        (2048 x 769, K=1538)  tf32 mma BN=64, 208 blocks
        k_mma128<4><<<dim3(13, 16), 256, 49152>>>(p_yp, LDA_OUT,
                                       p_wo + (size_t)l*DMODEL*LDA_OUT, LDA_OUT,
                                       p_h, DMODEL,
                                       BT, DMODEL, DINNER, 2);
    }

    k_layernorm<<<2048, 256>>>(lnw, lnb);
    k_classifier<<<2048, 320>>>(ow, ob, (float*)d_out);
}

// round 11
// speedup vs baseline: 1.0986x; 1.0986x over previous
#include <cuda_runtime.h>
#include <math.h>
#include <stdint.h>

#define NB 4
#define NT 512
#define DMODEL 769
#define DINNER 1538
#define DSTATE 64
#define DTRANK 49
#define BT (NB*NT)            // 2048 rows
#define XPROJ_N 177           // DT_RANK + 2*D_STATE
#define LDA_IN 800            // padded ld for in_proj operands (25 k-tiles)
#define LDA_OUT 1568          // padded ld for out_proj operands (49 k-tiles)

// ---------------- scratch (static device globals; zero-initialized) -------------
__device__ float g_xT [NB*64*NT];           // x transposed (B,64,T)
__device__ float g_h0 [NB*128*NT];          // pointconv out (B,128,T)
__device__ float g_h2 [NB*768*NT];          // conv stack out (B,768,T)
__device__ float g_h  [BT*DMODEL];          // residual stream (B,T,769)
__device__ __align__(16) float g_unp[BT*LDA_IN];        // normalized, padded ld 800
__device__ __align__(16) float g_wi [2*2*DINNER*LDA_IN];// in_proj W padded
__device__ __align__(16) float g_wo [2*DMODEL*LDA_OUT]; // out_proj W padded
__device__ __align__(16) float g_yp [BT*LDA_OUT];       // scan out, padded ld 1568
__device__ float g_xz [BT*2*DINNER];        // in_proj out (B,T,3076)
__device__ float g_xin[BT*DINNER];          // post dw-conv silu
__device__ float g_dbc[BT*XPROJ_N];         // x_proj out
__device__ float g_dt [BT*DINNER];          // softplus(dt)

__device__ __forceinline__ float silu_f(float v){ return v / (1.f + __expf(-v)); }

// ---- tf32 mma (raw-bit truncation; fp32 bits are valid tf32 input) ----
__device__ __forceinline__ void mma_tf32(float* c, const uint32_t* a, const uint32_t* b){
    asm("mma.sync.aligned.m16n8k8.row.col.f32.tf32.tf32.f32 "
        "{%0,%1,%2,%3}, {%4,%5,%6,%7}, {%8,%9}, {%0,%1,%2,%3};"
        : "+f"(c[0]), "+f"(c[1]), "+f"(c[2]), "+f"(c[3])
        : "r"(a[0]), "r"(a[1]), "r"(a[2]), "r"(a[3]), "r"(b[0]), "r"(b[1]));
}

// ---------------- weight repack into padded layout (pads stay zero) -------------
__global__ void k_packw(const float* __restrict__ src, float* __restrict__ dst,
                        int rows, int K, int ldd){
    int idx = blockIdx.x*256 + threadIdx.x;
    if (idx >= rows*K) return;
    int r = idx / K, c = idx - r*K;
    dst[(size_t)r*ldd + c] = src[idx];
}

// ---------------- x (B,T,65) -> g_xT (B,64,T) ----------------
__global__ void k_xt(const float* __restrict__ x){
    __shared__ float tile[32][33];
    int b  = blockIdx.z;
    int t0 = blockIdx.x*32, c0 = blockIdx.y*32;
    int tx = threadIdx.x, ty = threadIdx.y;
    tile[ty][tx] = x[(b*NT + t0 + ty)*65 + c0 + tx];
    __syncthreads();
    g_xT[(b*64 + c0 + ty)*NT + t0 + tx] = tile[tx][ty];
}

// ---------------- front: pointwise conv (64->128) + silu (coalesced) ------------
__global__ void k_pointconv(const float* __restrict__ pw,
                            const float* __restrict__ pb){
    int idx = blockIdx.x*256 + threadIdx.x;
    int t = idx & 511;
    int c = (idx >> 9) & 127;
    int b = idx >> 16;
    const float* xr = g_xT + b*64*NT + t;
    const float* wr = pw + c*64;
    float acc = pb[c];
#pragma unroll
    for (int i = 0; i < 64; i++) acc += xr[i*NT]*wr[i];
    g_h0[(b*128 + c)*NT + t] = silu_f(acc);
}

// ---- front conv v5: 8 ocs per block, T split in 4 quarters (grid 512) ----
template<int KS>
__global__ void k_conv(const float* __restrict__ w,
                       const float* __restrict__ bias,
                       int ocBase){
    __shared__ float ws[8][8*KS];
    __shared__ float xs[8][160];
    const int tid = threadIdx.x;
    const int b   = blockIdx.x >> 7;
    const int rem = blockIdx.x & 127;
    const int ocg = rem >> 2;
    const int tq  = rem & 3;
    const int oc0 = ocg*8;
    const int tbase = tq*128;
    const int pad = (KS - 1)/2;
    const int oc_sub = tid >> 7;
    const int tc  = tid & 127;

    float acc[4];
#pragma unroll
    for (int ol = 0; ol < 4; ol++) acc[ol] = bias[oc0 + oc_sub*4 + ol];

    for (int icb = 0; icb < 128; icb += 8){
        __syncthreads();
        for (int i = tid; i < 8*155; i += 256){
            int r = i / 155, j = i - r*155;
            int tt = tbase + j - 13;
            const float* hrow = g_h0 + (b*128 + icb + r)*NT;
            xs[r][j] = (tt >= 0 && tt < NT) ? hrow[tt] : 0.f;
        }
        for (int i = tid; i < 8*8*KS; i += 256){
            int oc = i / (8*KS), j = i - oc*(8*KS);
            ws[oc][j] = w[(oc0 + oc)*128*KS + icb*KS + j];
        }
        __syncthreads();
#pragma unroll
        for (int r = 0; r < 8; r++){
            float xv[KS];
            const int base = tc + 13 - pad;
#pragma unroll
            for (int q = 0; q < KS; q++) xv[q] = xs[r][base + q];
#pragma unroll
            for (int ol = 0; ol < 4; ol++){
                const float* wr = &ws[oc_sub*4 + ol][r*KS];
#pragma unroll
                for (int k = 0; k < KS; k++) acc[ol] += wr[k]*xv[k];
            }
        }
    }
#pragma unroll
    for (int ol = 0; ol < 4; ol++)
        g_h2[(b*768 + ocBase + oc0 + oc_sub*4 + ol)*NT + tbase + tc] = silu_f(acc[ol]);
}

// ---------------- (B,C,T) -> (B,T,769) transpose ----------------
__global__ void k_transpose(){
    __shared__ float tile[32][33];
    int b  = blockIdx.z;
    int t0 = blockIdx.x*32, c0 = blockIdx.y*32;
    int tx = threadIdx.x, ty = threadIdx.y;
    tile[ty][tx] = g_h2[(b*768 + c0 + ty)*NT + t0 + tx];
    __syncthreads();
    g_h[(b*NT + t0 + ty)*DMODEL + c0 + tx] = tile[tx][ty];
}

__global__ void k_pe(const float* __restrict__ x){
    int i = blockIdx.x*256 + threadIdx.x;
    if (i >= BT) return;
    g_h[i*DMODEL + 768] = x[i*65 + 64];
}

// ---------------- rmsnorm (writes padded g_unp) / layernorm ----------------
__global__ void k_rmsnorm(const float* __restrict__ w){
    int m = blockIdx.x, tid = threadIdx.x;
    const float* row = g_h + m*DMODEL;
    float s = 0.f;
    for (int k = tid; k < DMODEL; k += 256){ float v = row[k]; s += v*v; }
#pragma unroll
    for (int o = 16; o > 0; o >>= 1) s += __shfl_xor_sync(0xffffffffu, s, o);
    __shared__ float red[8];
    if ((tid & 31) == 0) red[tid >> 5] = s;
    __syncthreads();
    s = red[0]+red[1]+red[2]+red[3]+red[4]+red[5]+red[6]+red[7];
    float sc = rsqrtf(s/769.f + 1e-6f);
    float* o = g_unp + (size_t)m*LDA_IN;
    for (int k = tid; k < DMODEL; k += 256) o[k] = row[k]*sc*w[k];
}

__global__ void k_layernorm(const float* __restrict__ w, const float* __restrict__ bb){
    int m = blockIdx.x, tid = threadIdx.x;
    const float* row = g_h + m*DMODEL;
    float s1 = 0.f, s2 = 0.f;
    for (int k = tid; k < DMODEL; k += 256){ float v = row[k]; s1 += v; s2 += v*v; }
#pragma unroll
    for (int o = 16; o > 0; o >>= 1){
        s1 += __shfl_xor_sync(0xffffffffu, s1, o);
        s2 += __shfl_xor_sync(0xffffffffu, s2, o);
    }
    __shared__ float r1[8], r2[8];
    if ((tid & 31) == 0){ r1[tid >> 5] = s1; r2[tid >> 5] = s2; }
    __syncthreads();
    s1 = 0.f; s2 = 0.f;
#pragma unroll
    for (int i = 0; i < 8; i++){ s1 += r1[i]; s2 += r2[i]; }
    float mean = s1/769.f;
    float var  = s2/769.f - mean*mean;
    float istd = rsqrtf(var + 1e-5f);
    float* o = g_unp + (size_t)m*LDA_IN;
    for (int k = tid; k < DMODEL; k += 256)
        o[k] = (row[k] - mean)*istd*w[k] + bb[k];
}

// ---------------- tf32 MMA GEMM 128xBNx32, row-major smem (conflict-free) -------
// NJ = BN/16 (8 -> BN=128, 4 -> BN=64). Padded zero-filled operands.
// epi: 0 = store, 2 = C += acc
template<int NJ>
__global__ void __launch_bounds__(256, 2)
k_mma128(const float* __restrict__ A, int lda,
         const float* __restrict__ W, int ldw,
         float* __restrict__ C, int ldc,
         int M, int N, int K, int epi){
    __shared__ __align__(16) float As[128][36];
    __shared__ __align__(16) float Ws[NJ*16][36];
    const int BN = NJ*16;

    const int tid  = threadIdx.x;
    const int lane = tid & 31;
    const int wid  = tid >> 5;
    const int warp_m = wid & 3, warp_n = wid >> 2;
    const int m0 = blockIdx.y*128, n0 = blockIdx.x*BN;

    const int sr  = tid >> 1;           // 0..127
    const int skb = (tid & 1) * 16;

    const bool okA = (m0 + sr) < M;
    const bool stW = (sr < BN);
    const bool okW = stW && ((n0 + sr) < N);
    const float* Arow = A + (size_t)(m0 + sr)*lda + skb;
    const float* Wrow = W + (size_t)(n0 + sr)*ldw + skb;

    float acc[2][NJ][4];
#pragma unroll
    for (int i = 0; i < 2; i++)
#pragma unroll
        for (int j = 0; j < NJ; j++)
#pragma unroll
            for (int q = 0; q < 4; q++) acc[i][j][q] = 0.f;

    const int nk = (K + 31) >> 5;
    float4 ra4[4], rb4[4];

    // prefetch tile 0
#pragma unroll
    for (int q = 0; q < 4; q++){
        ra4[q] = okA ? ((const float4*)Arow)[q] : make_float4(0.f,0.f,0.f,0.f);
        rb4[q] = okW ? ((const float4*)Wrow)[q] : make_float4(0.f,0.f,0.f,0.f);
    }

    const int r_f = lane >> 2;          // fragment row/col group 0..7
    const int c_f = lane & 3;           // fragment k 0..3

    for (int kt = 0; kt < nk; kt++){
        __syncthreads();                // previous tile fully consumed
#pragma unroll
        for (int q = 0; q < 4; q++)
            *(float4*)&As[sr][skb + q*4] = ra4[q];
        if (stW){
#pragma unroll
            for (int q = 0; q < 4; q++)
                *(float4*)&Ws[sr][skb + q*4] = rb4[q];
        }
        __syncthreads();

        if (kt + 1 < nk){
            int k0 = (kt + 1)*32;
#pragma unroll
            for (int q = 0; q < 4; q++){
                ra4[q] = okA ? ((const float4*)(Arow + k0))[q] : make_float4(0.f,0.f,0.f,0.f);
                rb4[q] = okW ? ((const float4*)(Wrow + k0))[q] : make_float4(0.f,0.f,0.f,0.f);
            }
        }

#pragma unroll
        for (int kch = 0; kch < 4; kch++){
            uint32_t af[2][4], bf[NJ][2];
#pragma unroll
            for (int i = 0; i < 2; i++){
                const uint32_t* ar = (const uint32_t*)&As[warp_m*32 + i*16 + r_f][kch*8 + c_f];
                af[i][0] = ar[0];
                af[i][1] = ar[8*36];
                af[i][2] = ar[4];
                af[i][3] = ar[8*36 + 4];
            }
#pragma unroll
            for (int j = 0; j < NJ; j++){
                const uint32_t* br = (const uint32_t*)&Ws[warp_n*NJ*8 + j*8 + r_f][kch*8 + c_f];
                bf[j][0] = br[0];
                bf[j][1] = br[4];
            }
#pragma unroll
            for (int i = 0; i < 2; i++)
#pragma unroll
                for (int j = 0; j < NJ; j++) mma_tf32(acc[i][j], af[i], bf[j]);
        }
    }

    const int r_c = lane >> 2, c_c = (lane & 3)*2;
#pragma unroll
    for (int i = 0; i < 2; i++){
        int gmA0 = m0 + warp_m*32 + i*16 + r_c;
#pragma unroll
        for (int j = 0; j < NJ; j++){
            int gn = n0 + warp_n*(NJ*8) + j*8 + c_c;
#pragma unroll
            for (int h = 0; h < 2; h++){
                int gm = gmA0 + h*8;
                if (gm >= M) continue;
                float* crow = C + (size_t)gm*ldc;
                float v0 = acc[i][j][2*h], v1 = acc[i][j][2*h + 1];
                if (epi == 2){
                    if (gn     < N) crow[gn]     += v0;
                    if (gn + 1 < N) crow[gn + 1] += v1;
                } else {
                    if (gn     < N) crow[gn]     = v0;
                    if (gn + 1 < N) crow[gn + 1] = v1;
                }
            }
        }
    }
}

// ---------------- SGEMM 64x64 fp32: C = epi(A(MxK) * W(NxK)^T) ------------------
// epi: 0 = none, 1 = bias + softplus
__global__ void k_sgemm64(const float* __restrict__ A, int lda,
                          const float* __restrict__ W, int ldw,
                          float* __restrict__ C, int ldc,
                          int M, int N, int K,
                          const float* __restrict__ bias, int epi){
    __shared__ __align__(16) float As[16][68];
    __shared__ __align__(16) float Ws[16][68];
    const int tid = threadIdx.x;
    const int m0 = blockIdx.y*64, n0 = blockIdx.x*64;
    const int tx = tid & 15, ty = tid >> 4;

    float acc[4][4];
#pragma unroll
    for (int i = 0; i < 4; i++)
#pragma unroll
        for (int j = 0; j < 4; j++) acc[i][j] = 0.f;

    for (int k0 = 0; k0 < K; k0 += 16){
        for (int i = tid; i < 1024; i += 256){
            int mm = i >> 4, kk = i & 15;
            int gk = k0 + kk;
            int gm = m0 + mm;
            As[kk][mm] = (gm < M && gk < K) ? A[gm*lda + gk] : 0.f;
            int gn = n0 + mm;
            Ws[kk][mm] = (gn < N && gk < K) ? W[gn*ldw + gk] : 0.f;
        }
        __syncthreads();
#pragma unroll
        for (int kk = 0; kk < 16; kk++){
            float4 a4 = *(const float4*)&As[kk][ty*4];
            float4 w4 = *(const float4*)&Ws[kk][tx*4];
            float av[4] = {a4.x, a4.y, a4.z, a4.w};
            float wv[4] = {w4.x, w4.y, w4.z, w4.w};
#pragma unroll
            for (int i = 0; i < 4; i++)
#pragma unroll
                for (int j = 0; j < 4; j++) acc[i][j] += av[i]*wv[j];
        }
        __syncthreads();
    }

#pragma unroll
    for (int i = 0; i < 4; i++){
        int gm = m0 + ty*4 + i;
        if (gm >= M) continue;
#pragma unroll
        for (int j = 0; j < 4; j++){
            int gn = n0 + tx*4 + j;
            if (gn >= N) continue;
            float v = acc[i][j];
            float* cp = &C[gm*ldc + gn];
            if (epi == 1){
                v += bias[gn];
                v = fmaxf(v, 0.f) + log1pf(expf(-fabsf(v)));   // stable softplus
                *cp = v;
            } else {
                *cp = v;
            }
        }
    }
}

// ---------------- depthwise causal conv (k=4) + silu ----------------
__global__ void k_dwconv(const float* __restrict__ cw, const float* __restrict__ cb){
    int idx = blockIdx.x*256 + threadIdx.x;
    int d  = idx % DINNER;
    int bt = idx / DINNER;
    int t  = bt & 511;
    float acc = cb[d];
#pragma unroll
    for (int k = 0; k < 4; k++){
        int tt = t - 3 + k;
        if (tt >= 0) acc += cw[d*4 + k] * g_xz[(bt - 3 + k)*2*DINNER + d];
    }
    g_xin[bt*DINNER + d] = silu_f(acc);
}

// ---------------- selective scan: warp per (b,d), 2 states/lane ----------------
__global__ void k_scan(const float* __restrict__ Alog, const float* __restrict__ Dv){
    int w    = blockIdx.x*4 + (threadIdx.x >> 5);
    int lane = threadIdx.x & 31;
    int b = w & 3;
    int d = w >> 2;

    float A1 = -__expf(Alog[d*64 + lane]);
    float A2 = -__expf(Alog[d*64 + lane + 32]);
    float Dd = Dv[d];
    float h1 = 0.f, h2 = 0.f;

    int r = b*NT;
    for (int t = 0; t < NT; t++, r++){
        float dtv = g_dt [r*DINNER + d];
        float uv  = g_xin[r*DINNER + d];
        const float* q = g_dbc + r*XPROJ_N;
        float B1 = q[49  + lane], B2 = q[81  + lane];
        float C1 = q[113 + lane], C2 = q[145 + lane];
        float du = dtv*uv;
        h1 = __expf(dtv*A1)*h1 + du*B1;
        h2 = __expf(dtv*A2)*h2 + du*B2;
        float p = h1*C1 + h2*C2;
#pragma unroll
        for (int o = 16; o > 0; o >>= 1) p += __shfl_xor_sync(0xffffffffu, p, o);
        if (lane == 0){
            float zv = g_xz[r*2*DINNER + DINNER + d];
            g_yp[(size_t)r*LDA_OUT + d] = (p + uv*Dd) * silu_f(zv);
        }
    }
}

// ---------------- classifier: warp per (row, class) ----------------
__global__ void k_classifier(const float* __restrict__ ow,
                             const float* __restrict__ ob,
                             float* __restrict__ out){
    int m = blockIdx.x;
    int wid  = threadIdx.x >> 5;
    int lane = threadIdx.x & 31;
    const float* u  = g_unp + (size_t)m*LDA_IN;
    const float* wr = ow + wid*DMODEL;
    float s = 0.f;
    for (int k = lane; k < DMODEL; k += 32) s += u[k]*wr[k];
#pragma unroll
    for (int o = 16; o > 0; o >>= 1) s += __shfl_xor_sync(0xffffffffu, s, o);
    if (lane == 0) out[m*10 + wid] = s + ob[wid];
}

// ---------------- orchestration ----------------
extern "C" void kernel_launch(void* const* d_in, const int* in_sizes, int n_in,
                              void* d_out, int out_size){
    const float* x    = (const float*)d_in[0];
    const float* pw   = (const float*)d_in[1];
    const float* pb   = (const float*)d_in[2];
    const float* c1w  = (const float*)d_in[3];
    const float* c1b  = (const float*)d_in[4];
    const float* c2w  = (const float*)d_in[5];
    const float* c2b  = (const float*)d_in[6];
    const float* c3w  = (const float*)d_in[7];
    const float* c3b  = (const float*)d_in[8];
    const float* lnw  = (const float*)d_in[9];
    const float* lnb  = (const float*)d_in[10];
    const float* ow   = (const float*)d_in[11];
    const float* ob   = (const float*)d_in[12];
    const float* rmsw = (const float*)d_in[13];
    const float* inw  = (const float*)d_in[14];
    const float* dww  = (const float*)d_in[15];
    const float* dwb  = (const float*)d_in[16];
    const float* xpw  = (const float*)d_in[17];
    const float* dtw  = (const float*)d_in[18];
    const float* dtb  = (const float*)d_in[19];
    const float* alog = (const float*)d_in[20];
    const float* dsk  = (const float*)d_in[21];
    const float* opw  = (const float*)d_in[22];

    float *p_unp, *p_xz, *p_xin, *p_dbc, *p_dt, *p_yp, *p_h, *p_wi, *p_wo;
    cudaGetSymbolAddress((void**)&p_unp, g_unp);
    cudaGetSymbolAddress((void**)&p_xz,  g_xz);
    cudaGetSymbolAddress((void**)&p_xin, g_xin);
    cudaGetSymbolAddress((void**)&p_dbc, g_dbc);
    cudaGetSymbolAddress((void**)&p_dt,  g_dt);
    cudaGetSymbolAddress((void**)&p_yp,  g_yp);
    cudaGetSymbolAddress((void**)&p_h,   g_h);
    cudaGetSymbolAddress((void**)&p_wi,  g_wi);
    cudaGetSymbolAddress((void**)&p_wo,  g_wo);

    // weight repacks into padded layout (pads stay zero from static init)
    k_packw<<<(2*2*DINNER*DMODEL + 255)/256, 256>>>(inw, p_wi, 2*2*DINNER, DMODEL, LDA_IN);
    k_packw<<<(2*DMODEL*DINNER + 255)/256, 256>>>(opw, p_wo, 2*DMODEL, DINNER, LDA_OUT);

    k_xt<<<dim3(16, 2, 4), dim3(32, 32)>>>(x);
    k_pointconv<<<1024, 256>>>(pw, pb);
    k_conv<3> <<<512, 256>>>(c1w, c1b, 0);
    k_conv<9> <<<512, 256>>>(c2w, c2b, 256);
    k_conv<27><<<512, 256>>>(c3w, c3b, 512);
    k_transpose<<<dim3(16, 24, 4), dim3(32, 32)>>>();
    k_pe<<<8, 256>>>(x);

    for (int l = 0; l < 2; l++){
        k_rmsnorm<<<2048, 256>>>(rmsw + l*DMODEL);
        // xz = un @ Wi^T       (2048 x 3076, K=769)  tf32 mma BN=128, 400 blocks
        k_mma128<8><<<dim3(25, 16), 256>>>(p_unp, LDA_IN,
                                        p_wi + (size_t)l*2*DINNER*LDA_IN, LDA_IN,
                                        p_xz, 2*DINNER,
                                        BT, 2*DINNER, DMODEL, 0);
        k_dwconv<<<12304, 256>>>(dww + l*DINNER*4, dwb + l*DINNER);
        // dbc = xin @ Wx^T     (2048 x 177, K=1538)  fp32 64x64
        k_sgemm64<<<dim3(3, 32), 256>>>(p_xin, DINNER,
                                        xpw + (size_t)l*XPROJ_N*DINNER, DINNER,
                                        p_dbc, XPROJ_N,
                                        BT, XPROJ_N, DINNER, nullptr, 0);
        // dt = softplus(dbc[:, :49] @ Wdt^T + bdt)   (2048 x 1538, K=49)
        k_sgemm64<<<dim3(25, 32), 256>>>(p_dbc, XPROJ_N,
                                         dtw + (size_t)l*DINNER*DTRANK, DTRANK,
                                         p_dt, DINNER,
                                         BT, DINNER, DTRANK, dtb + l*DINNER, 1);
        k_scan<<<1538, 128>>>(alog + (size_t)l*DINNER*DSTATE, dsk + l*DINNER);
        // h += y @ Wo^T        (2048 x 769, K=1538)  tf32 mma BN=64, 208 blocks
        k_mma128<4><<<dim3(13, 16), 256>>>(p_yp, LDA_OUT,
                                       p_wo + (size_t)l*DMODEL*LDA_OUT, LDA_OUT,
                                       p_h, DMODEL,
                                       BT, DMODEL, DINNER, 2);
    }

    k_layernorm<<<2048, 256>>>(lnw, lnb);
    k_classifier<<<2048, 320>>>(ow, ob, (float*)d_out);
}

// round 12
// speedup vs baseline: 1.3176x; 1.1993x over previous
#include <cuda_runtime.h>
#include <math.h>
#include <stdint.h>

#define NB 4
#define NT 512
#define DMODEL 769
#define DINNER 1538
#define DSTATE 64
#define DTRANK 49
#define BT (NB*NT)            // 2048 rows
#define XPROJ_N 177           // DT_RANK + 2*D_STATE
#define LDA_IN 800            // padded ld (25 k-tiles of 32)
#define LDA_OUT 1568          // padded ld (49 k-tiles of 32)

// ---------------- scratch (static device globals; zero-initialized) -------------
__device__ float g_xT [NB*64*NT];
__device__ float g_h0 [NB*128*NT];
__device__ float g_h2 [NB*768*NT];
__device__ float g_h  [BT*DMODEL];
__device__ __align__(16) float g_unp [BT*LDA_IN];         // rmsnorm out (rna tf32) / layernorm out (fp32)
__device__ __align__(16) float g_wi  [2*2*DINNER*LDA_IN]; // in_proj W padded (rna)
__device__ __align__(16) float g_wo  [2*DMODEL*LDA_OUT];  // out_proj W padded (rna)
__device__ __align__(16) float g_wx  [2*XPROJ_N*LDA_OUT]; // x_proj W padded (rna)
__device__ __align__(16) float g_xinp[BT*LDA_OUT];        // dwconv out, padded (rna)
__device__ __align__(16) float g_yp  [BT*LDA_OUT];        // scan out, padded (rna)
__device__ float g_xz [BT*2*DINNER];
__device__ float g_dbc[BT*XPROJ_N];
__device__ float g_dt [BT*DINNER];

__device__ __forceinline__ float silu_f(float v){ return v / (1.f + __expf(-v)); }
__device__ __forceinline__ float tf32r(float v){
    uint32_t r; asm("cvt.rna.tf32.f32 %0, %1;" : "=r"(r) : "f"(v));
    return __uint_as_float(r);
}

// ---- tf32 mma (operands pre-rounded by producers) ----
__device__ __forceinline__ void mma_tf32(float* c, const uint32_t* a, const uint32_t* b){
    asm("mma.sync.aligned.m16n8k8.row.col.f32.tf32.tf32.f32 "
        "{%0,%1,%2,%3}, {%4,%5,%6,%7}, {%8,%9}, {%0,%1,%2,%3};"
        : "+f"(c[0]), "+f"(c[1]), "+f"(c[2]), "+f"(c[3])
        : "r"(a[0]), "r"(a[1]), "r"(a[2]), "r"(a[3]), "r"(b[0]), "r"(b[1]));
}

// ---------------- weight repack into padded layout, rna tf32 rounding -----------
__global__ void k_packw(const float* __restrict__ src, float* __restrict__ dst,
                        int rows, int K, int ldd){
    int idx = blockIdx.x*256 + threadIdx.x;
    if (idx >= rows*K) return;
    int r = idx / K, c = idx - r*K;
    dst[(size_t)r*ldd + c] = tf32r(src[idx]);
}

// ---------------- x (B,T,65) -> g_xT (B,64,T) ----------------
__global__ void k_xt(const float* __restrict__ x){
    __shared__ float tile[32][33];
    int b  = blockIdx.z;
    int t0 = blockIdx.x*32, c0 = blockIdx.y*32;
    int tx = threadIdx.x, ty = threadIdx.y;
    tile[ty][tx] = x[(b*NT + t0 + ty)*65 + c0 + tx];
    __syncthreads();
    g_xT[(b*64 + c0 + ty)*NT + t0 + tx] = tile[tx][ty];
}

// ---------------- front: pointwise conv (64->128) + silu ----------------
__global__ void k_pointconv(const float* __restrict__ pw,
                            const float* __restrict__ pb){
    int idx = blockIdx.x*256 + threadIdx.x;
    int t = idx & 511;
    int c = (idx >> 9) & 127;
    int b = idx >> 16;
    const float* xr = g_xT + b*64*NT + t;
    const float* wr = pw + c*64;
    float acc = pb[c];
#pragma unroll
    for (int i = 0; i < 64; i++) acc += xr[i*NT]*wr[i];
    g_h0[(b*128 + c)*NT + t] = silu_f(acc);
}

// ---- front conv v5: 8 ocs per block, T split in 4 quarters (grid 512) ----
template<int KS>
__global__ void k_conv(const float* __restrict__ w,
                       const float* __restrict__ bias,
                       int ocBase){
    __shared__ float ws[8][8*KS];
    __shared__ float xs[8][160];
    const int tid = threadIdx.x;
    const int b   = blockIdx.x >> 7;
    const int rem = blockIdx.x & 127;
    const int ocg = rem >> 2;
    const int tq  = rem & 3;
    const int oc0 = ocg*8;
    const int tbase = tq*128;
    const int pad = (KS - 1)/2;
    const int oc_sub = tid >> 7;
    const int tc  = tid & 127;

    float acc[4];
#pragma unroll
    for (int ol = 0; ol < 4; ol++) acc[ol] = bias[oc0 + oc_sub*4 + ol];

    for (int icb = 0; icb < 128; icb += 8){
        __syncthreads();
        for (int i = tid; i < 8*155; i += 256){
            int r = i / 155, j = i - r*155;
            int tt = tbase + j - 13;
            const float* hrow = g_h0 + (b*128 + icb + r)*NT;
            xs[r][j] = (tt >= 0 && tt < NT) ? hrow[tt] : 0.f;
        }
        for (int i = tid; i < 8*8*KS; i += 256){
            int oc = i / (8*KS), j = i - oc*(8*KS);
            ws[oc][j] = w[(oc0 + oc)*128*KS + icb*KS + j];
        }
        __syncthreads();
#pragma unroll
        for (int r = 0; r < 8; r++){
            float xv[KS];
            const int base = tc + 13 - pad;
#pragma unroll
            for (int q = 0; q < KS; q++) xv[q] = xs[r][base + q];
#pragma unroll
            for (int ol = 0; ol < 4; ol++){
                const float* wr = &ws[oc_sub*4 + ol][r*KS];
#pragma unroll
                for (int k = 0; k < KS; k++) acc[ol] += wr[k]*xv[k];
            }
        }
    }
#pragma unroll
    for (int ol = 0; ol < 4; ol++)
        g_h2[(b*768 + ocBase + oc0 + oc_sub*4 + ol)*NT + tbase + tc] = silu_f(acc[ol]);
}

// ---------------- (B,C,T) -> (B,T,769) transpose ----------------
__global__ void k_transpose(){
    __shared__ float tile[32][33];
    int b  = blockIdx.z;
    int t0 = blockIdx.x*32, c0 = blockIdx.y*32;
    int tx = threadIdx.x, ty = threadIdx.y;
    tile[ty][tx] = g_h2[(b*768 + c0 + ty)*NT + t0 + tx];
    __syncthreads();
    g_h[(b*NT + t0 + ty)*DMODEL + c0 + tx] = tile[tx][ty];
}

__global__ void k_pe(const float* __restrict__ x){
    int i = blockIdx.x*256 + threadIdx.x;
    if (i >= BT) return;
    g_h[i*DMODEL + 768] = x[i*65 + 64];
}

// ---------------- rmsnorm (rna tf32 out, padded) / layernorm (exact) ------------
__global__ void k_rmsnorm(const float* __restrict__ w){
    int m = blockIdx.x, tid = threadIdx.x;
    const float* row = g_h + m*DMODEL;
    float s = 0.f;
    for (int k = tid; k < DMODEL; k += 256){ float v = row[k]; s += v*v; }
#pragma unroll
    for (int o = 16; o > 0; o >>= 1) s += __shfl_xor_sync(0xffffffffu, s, o);
    __shared__ float red[8];
    if ((tid & 31) == 0) red[tid >> 5] = s;
    __syncthreads();
    s = red[0]+red[1]+red[2]+red[3]+red[4]+red[5]+red[6]+red[7];
    float sc = rsqrtf(s/769.f + 1e-6f);
    float* o = g_unp + (size_t)m*LDA_IN;
    for (int k = tid; k < DMODEL; k += 256) o[k] = tf32r(row[k]*sc*w[k]);
}

__global__ void k_layernorm(const float* __restrict__ w, const float* __restrict__ bb){
    int m = blockIdx.x, tid = threadIdx.x;
    const float* row = g_h + m*DMODEL;
    float s1 = 0.f, s2 = 0.f;
    for (int k = tid; k < DMODEL; k += 256){ float v = row[k]; s1 += v; s2 += v*v; }
#pragma unroll
    for (int o = 16; o > 0; o >>= 1){
        s1 += __shfl_xor_sync(0xffffffffu, s1, o);
        s2 += __shfl_xor_sync(0xffffffffu, s2, o);
    }
    __shared__ float r1[8], r2[8];
    if ((tid & 31) == 0){ r1[tid >> 5] = s1; r2[tid >> 5] = s2; }
    __syncthreads();
    s1 = 0.f; s2 = 0.f;
#pragma unroll
    for (int i = 0; i < 8; i++){ s1 += r1[i]; s2 += r2[i]; }
    float mean = s1/769.f;
    float var  = s2/769.f - mean*mean;
    float istd = rsqrtf(var + 1e-5f);
    float* o = g_unp + (size_t)m*LDA_IN;
    for (int k = tid; k < DMODEL; k += 256)
        o[k] = (row[k] - mean)*istd*w[k] + bb[k];
}

// ---------------- tf32 MMA GEMM 128xBNx32, row-major smem (conflict-free) -------
// NJ = BN/16. Padded zero-filled operands. epi: 0 = store, 2 = C += acc
template<int NJ>
__global__ void __launch_bounds__(256, 2)
k_mma128(const float* __restrict__ A, int lda,
         const float* __restrict__ W, int ldw,
         float* __restrict__ C, int ldc,
         int M, int N, int K, int epi){
    __shared__ __align__(16) float As[128][36];
    __shared__ __align__(16) float Ws[NJ*16][36];
    const int BN = NJ*16;

    const int tid  = threadIdx.x;
    const int lane = tid & 31;
    const int wid  = tid >> 5;
    const int warp_m = wid & 3, warp_n = wid >> 2;
    const int m0 = blockIdx.y*128, n0 = blockIdx.x*BN;

    const int sr  = tid >> 1;
    const int skb = (tid & 1) * 16;

    const bool okA = (m0 + sr) < M;
    const bool stW = (sr < BN);
    const bool okW = stW && ((n0 + sr) < N);
    const float* Arow = A + (size_t)(m0 + sr)*lda + skb;
    const float* Wrow = W + (size_t)(n0 + sr)*ldw + skb;

    float acc[2][NJ][4];
#pragma unroll
    for (int i = 0; i < 2; i++)
#pragma unroll
        for (int j = 0; j < NJ; j++)
#pragma unroll
            for (int q = 0; q < 4; q++) acc[i][j][q] = 0.f;

    const int nk = (K + 31) >> 5;
    float4 ra4[4], rb4[4];

#pragma unroll
    for (int q = 0; q < 4; q++){
        ra4[q] = okA ? ((const float4*)Arow)[q] : make_float4(0.f,0.f,0.f,0.f);
        rb4[q] = okW ? ((const float4*)Wrow)[q] : make_float4(0.f,0.f,0.f,0.f);
    }

    const int r_f = lane >> 2;
    const int c_f = lane & 3;

    for (int kt = 0; kt < nk; kt++){
        __syncthreads();
#pragma unroll
        for (int q = 0; q < 4; q++)
            *(float4*)&As[sr][skb + q*4] = ra4[q];
        if (stW){
#pragma unroll
            for (int q = 0; q < 4; q++)
                *(float4*)&Ws[sr][skb + q*4] = rb4[q];
        }
        __syncthreads();

        if (kt + 1 < nk){
            int k0 = (kt + 1)*32;
#pragma unroll
            for (int q = 0; q < 4; q++){
                ra4[q] = okA ? ((const float4*)(Arow + k0))[q] : make_float4(0.f,0.f,0.f,0.f);
                rb4[q] = okW ? ((const float4*)(Wrow + k0))[q] : make_float4(0.f,0.f,0.f,0.f);
            }
        }

#pragma unroll
        for (int kch = 0; kch < 4; kch++){
            uint32_t af[2][4], bf[NJ][2];
#pragma unroll
            for (int i = 0; i < 2; i++){
                const uint32_t* ar = (const uint32_t*)&As[warp_m*32 + i*16 + r_f][kch*8 + c_f];
                af[i][0] = ar[0];
                af[i][1] = ar[8*36];
                af[i][2] = ar[4];
                af[i][3] = ar[8*36 + 4];
            }
#pragma unroll
            for (int j = 0; j < NJ; j++){
                const uint32_t* br = (const uint32_t*)&Ws[warp_n*NJ*8 + j*8 + r_f][kch*8 + c_f];
                bf[j][0] = br[0];
                bf[j][1] = br[4];
            }
#pragma unroll
            for (int i = 0; i < 2; i++)
#pragma unroll
                for (int j = 0; j < NJ; j++) mma_tf32(acc[i][j], af[i], bf[j]);
        }
    }

    const int r_c = lane >> 2, c_c = (lane & 3)*2;
#pragma unroll
    for (int i = 0; i < 2; i++){
        int gmA0 = m0 + warp_m*32 + i*16 + r_c;
#pragma unroll
        for (int j = 0; j < NJ; j++){
            int gn = n0 + warp_n*(NJ*8) + j*8 + c_c;
#pragma unroll
            for (int h = 0; h < 2; h++){
                int gm = gmA0 + h*8;
                if (gm >= M) continue;
                float* crow = C + (size_t)gm*ldc;
                float v0 = acc[i][j][2*h], v1 = acc[i][j][2*h + 1];
                if (epi == 2){
                    if (gn     < N) crow[gn]     += v0;
                    if (gn + 1 < N) crow[gn + 1] += v1;
                } else {
                    if (gn     < N) crow[gn]     = v0;
                    if (gn + 1 < N) crow[gn + 1] = v1;
                }
            }
        }
    }
}

// ---------------- SGEMM 64x64 fp32 (dt GEMM): epi 1 = bias + fast softplus ------
__global__ void k_sgemm64(const float* __restrict__ A, int lda,
                          const float* __restrict__ W, int ldw,
                          float* __restrict__ C, int ldc,
                          int M, int N, int K,
                          const float* __restrict__ bias, int epi){
    __shared__ __align__(16) float As[16][68];
    __shared__ __align__(16) float Ws[16][68];
    const int tid = threadIdx.x;
    const int m0 = blockIdx.y*64, n0 = blockIdx.x*64;
    const int tx = tid & 15, ty = tid >> 4;

    float acc[4][4];
#pragma unroll
    for (int i = 0; i < 4; i++)
#pragma unroll
        for (int j = 0; j < 4; j++) acc[i][j] = 0.f;

    for (int k0 = 0; k0 < K; k0 += 16){
        for (int i = tid; i < 1024; i += 256){
            int mm = i >> 4, kk = i & 15;
            int gk = k0 + kk;
            int gm = m0 + mm;
            As[kk][mm] = (gm < M && gk < K) ? A[gm*lda + gk] : 0.f;
            int gn = n0 + mm;
            Ws[kk][mm] = (gn < N && gk < K) ? W[gn*ldw + gk] : 0.f;
        }
        __syncthreads();
#pragma unroll
        for (int kk = 0; kk < 16; kk++){
            float4 a4 = *(const float4*)&As[kk][ty*4];
            float4 w4 = *(const float4*)&Ws[kk][tx*4];
            float av[4] = {a4.x, a4.y, a4.z, a4.w};
            float wv[4] = {w4.x, w4.y, w4.z, w4.w};
#pragma unroll
            for (int i = 0; i < 4; i++)
#pragma unroll
                for (int j = 0; j < 4; j++) acc[i][j] += av[i]*wv[j];
        }
        __syncthreads();
    }

#pragma unroll
    for (int i = 0; i < 4; i++){
        int gm = m0 + ty*4 + i;
        if (gm >= M) continue;
#pragma unroll
        for (int j = 0; j < 4; j++){
            int gn = n0 + tx*4 + j;
            if (gn >= N) continue;
            float v = acc[i][j];
            float* cp = &C[gm*ldc + gn];
            if (epi == 1){
                v += bias[gn];
                // fast stable softplus: MUFU-based, ~1e-7 rel err
                v = fmaxf(v, 0.f) + __logf(1.f + __expf(-fabsf(v)));
                *cp = v;
            } else {
                *cp = v;
            }
        }
    }
}

// ---------------- depthwise causal conv (k=4) + silu -> padded rna out ----------
__global__ void k_dwconv(const float* __restrict__ cw, const float* __restrict__ cb){
    int idx = blockIdx.x*256 + threadIdx.x;
    int d  = idx % DINNER;
    int bt = idx / DINNER;
    int t  = bt & 511;
    float acc = cb[d];
#pragma unroll
    for (int k = 0; k < 4; k++){
        int tt = t - 3 + k;
        if (tt >= 0) acc += cw[d*4 + k] * g_xz[(bt - 3 + k)*2*DINNER + d];
    }
    g_xinp[(size_t)bt*LDA_OUT + d] = tf32r(silu_f(acc));
}

// ---------------- selective scan: warp per (b,d), 2 states/lane ----------------
__global__ void k_scan(const float* __restrict__ Alog, const float* __restrict__ Dv){
    int w    = blockIdx.x*4 + (threadIdx.x >> 5);
    int lane = threadIdx.x & 31;
    int b = w & 3;
    int d = w >> 2;

    float A1 = -__expf(Alog[d*64 + lane]);
    float A2 = -__expf(Alog[d*64 + lane + 32]);
    float Dd = Dv[d];
    float h1 = 0.f, h2 = 0.f;

    int r = b*NT;
    for (int t = 0; t < NT; t++, r++){
        float dtv = g_dt  [r*DINNER + d];
        float uv  = g_xinp[(size_t)r*LDA_OUT + d];
        const float* q = g_dbc + r*XPROJ_N;
        float B1 = q[49  + lane], B2 = q[81  + lane];
        float C1 = q[113 + lane], C2 = q[145 + lane];
        float du = dtv*uv;
        h1 = __expf(dtv*A1)*h1 + du*B1;
        h2 = __expf(dtv*A2)*h2 + du*B2;
        float p = h1*C1 + h2*C2;
#pragma unroll
        for (int o = 16; o > 0; o >>= 1) p += __shfl_xor_sync(0xffffffffu, p, o);
        if (lane == 0){
            float zv = g_xz[r*2*DINNER + DINNER + d];
            g_yp[(size_t)r*LDA_OUT + d] = tf32r((p + uv*Dd) * silu_f(zv));
        }
    }
}

// ---------------- classifier: warp per (row, class) ----------------
__global__ void k_classifier(const float* __restrict__ ow,
                             const float* __restrict__ ob,
                             float* __restrict__ out){
    int m = blockIdx.x;
    int wid  = threadIdx.x >> 5;
    int lane = threadIdx.x & 31;
    const float* u  = g_unp + (size_t)m*LDA_IN;
    const float* wr = ow + wid*DMODEL;
    float s = 0.f;
    for (int k = lane; k < DMODEL; k += 32) s += u[k]*wr[k];
#pragma unroll
    for (int o = 16; o > 0; o >>= 1) s += __shfl_xor_sync(0xffffffffu, s, o);
    if (lane == 0) out[m*10 + wid] = s + ob[wid];
}

// ---------------- orchestration ----------------
extern "C" void kernel_launch(void* const* d_in, const int* in_sizes, int n_in,
                              void* d_out, int out_size){
    const float* x    = (const float*)d_in[0];
    const float* pw   = (const float*)d_in[1];
    const float* pb   = (const float*)d_in[2];
    const float* c1w  = (const float*)d_in[3];
    const float* c1b  = (const float*)d_in[4];
    const float* c2w  = (const float*)d_in[5];
    const float* c2b  = (const float*)d_in[6];
    const float* c3w  = (const float*)d_in[7];
    const float* c3b  = (const float*)d_in[8];
    const float* lnw  = (const float*)d_in[9];
    const float* lnb  = (const float*)d_in[10];
    const float* ow   = (const float*)d_in[11];
    const float* ob   = (const float*)d_in[12];
    const float* rmsw = (const float*)d_in[13];
    const float* inw  = (const float*)d_in[14];
    const float* dww  = (const float*)d_in[15];
    const float* dwb  = (const float*)d_in[16];
    const float* xpw  = (const float*)d_in[17];
    const float* dtw  = (const float*)d_in[18];
    const float* dtb  = (const float*)d_in[19];
    const float* alog = (const float*)d_in[20];
    const float* dsk  = (const float*)d_in[21];
    const float* opw  = (const float*)d_in[22];

    float *p_unp, *p_xz, *p_xinp, *p_dbc, *p_dt, *p_yp, *p_h, *p_wi, *p_wo, *p_wx;
    cudaGetSymbolAddress((void**)&p_unp,  g_unp);
    cudaGetSymbolAddress((void**)&p_xz,   g_xz);
    cudaGetSymbolAddress((void**)&p_xinp, g_xinp);
    cudaGetSymbolAddress((void**)&p_dbc,  g_dbc);
    cudaGetSymbolAddress((void**)&p_dt,   g_dt);
    cudaGetSymbolAddress((void**)&p_yp,   g_yp);
    cudaGetSymbolAddress((void**)&p_h,    g_h);
    cudaGetSymbolAddress((void**)&p_wi,   g_wi);
    cudaGetSymbolAddress((void**)&p_wo,   g_wo);
    cudaGetSymbolAddress((void**)&p_wx,   g_wx);

    // weight repacks into padded layout, rna tf32 rounding (pads stay zero)
    k_packw<<<(2*2*DINNER*DMODEL + 255)/256, 256>>>(inw, p_wi, 2*2*DINNER, DMODEL, LDA_IN);
    k_packw<<<(2*DMODEL*DINNER + 255)/256, 256>>>(opw, p_wo, 2*DMODEL, DINNER, LDA_OUT);
    k_packw<<<(2*XPROJ_N*DINNER + 255)/256, 256>>>(xpw, p_wx, 2*XPROJ_N, DINNER, LDA_OUT);

    k_xt<<<dim3(16, 2, 4), dim3(32, 32)>>>(x);
    k_pointconv<<<1024, 256>>>(pw, pb);
    k_conv<3> <<<512, 256>>>(c1w, c1b, 0);
    k_conv<9> <<<512, 256>>>(c2w, c2b, 256);
    k_conv<27><<<512, 256>>>(c3w, c3b, 512);
    k_transpose<<<dim3(16, 24, 4), dim3(32, 32)>>>();
    k_pe<<<8, 256>>>(x);

    for (int l = 0; l < 2; l++){
        k_rmsnorm<<<2048, 256>>>(rmsw + l*DMODEL);
        // xz = un @ Wi^T       (2048 x 3076, K=769)  tf32 mma BN=128, 400 blocks
        k_mma128<8><<<dim3(25, 16), 256>>>(p_unp, LDA_IN,
                                        p_wi + (size_t)l*2*DINNER*LDA_IN, LDA_IN,
                                        p_xz, 2*DINNER,
                                        BT, 2*DINNER, DMODEL, 0);
        k_dwconv<<<12304, 256>>>(dww + l*DINNER*4, dwb + l*DINNER);
        // dbc = xin @ Wx^T     (2048 x 177, K=1538)  tf32 mma BN=64, 48 blocks
        k_mma128<4><<<dim3(3, 16), 256>>>(p_xinp, LDA_OUT,
                                        p_wx + (size_t)l*XPROJ_N*LDA_OUT, LDA_OUT,
                                        p_dbc, XPROJ_N,
                                        BT, XPROJ_N, DINNER, 0);
        // dt = softplus(dbc[:, :49] @ Wdt^T + bdt)   (2048 x 1538, K=49)  fp32
        k_sgemm64<<<dim3(25, 32), 256>>>(p_dbc, XPROJ_N,
                                         dtw + (size_t)l*DINNER*DTRANK, DTRANK,
                                         p_dt, DINNER,
                                         BT, DINNER, DTRANK, dtb + l*DINNER, 1);
        k_scan<<<1538, 128>>>(alog + (size_t)l*DINNER*DSTATE, dsk + l*DINNER);
        // h += y @ Wo^T        (2048 x 769, K=1538)  tf32 mma BN=64, 208 blocks
        k_mma128<4><<<dim3(13, 16), 256>>>(p_yp, LDA_OUT,
                                       p_wo + (size_t)l*DMODEL*LDA_OUT, LDA_OUT,
                                       p_h, DMODEL,
                                       BT, DMODEL, DINNER, 2);
    }

    k_layernorm<<<2048, 256>>>(lnw, lnb);
    k_classifier<<<2048, 320>>>(ow, ob, (float*)d_out);
}